// round 15
// baseline (speedup 1.0000x reference)
#include <cuda_runtime.h>
#include <cstdint>

#define B_ 4
#define L_ 2048
#define H_ 16
#define DH_ 64
#define DM_ 1024
#define N3_ 3072
#define BH_ (B_*H_)
#define OUT_ELEMS_ (B_*L_*DM_)   // 8388608

// Scratch (device globals: allocation-free per harness rules)
__device__ float g_q[BH_*L_*DH_];     // fp32
__device__ float g_k[BH_*L_*DH_];     // fp32 (split to tf32 hi/lo in regs)
__device__ float g_v[BH_*L_*DH_];     // pre-rounded tf32 (rna)

// tf32 hi/lo decompositions for projections
__device__ float g_xhi[B_*L_*DM_];
__device__ float g_xlo[B_*L_*DM_];
__device__ float g_wqhi[N3_*DM_];    // [n][k] (transposed W_qkv)
__device__ float g_wqlo[N3_*DM_];
__device__ float g_wohi[DM_*DM_];    // [n][k] (transposed W_out)
__device__ float g_wolo[DM_*DM_];
__device__ float g_hhi[B_*L_*DM_];   // attn writes hout pre-split
__device__ float g_hlo[B_*L_*DM_];

// ---------------------------------------------------------------------------
// Helpers
// ---------------------------------------------------------------------------
__device__ __forceinline__ uint32_t smem_u32(const void* p) {
    uint32_t a;
    asm("{ .reg .u64 t; cvta.to.shared.u64 t, %1; cvt.u32.u64 %0, t; }"
        : "=r"(a) : "l"(p));
    return a;
}
__device__ __forceinline__ void cpa16(uint32_t dst, const float* src) {
    asm volatile("cp.async.cg.shared.global [%0], [%1], 16;" :: "r"(dst), "l"(src));
}
__device__ __forceinline__ float2 tf32split(float a) {
    uint32_t hb;
    asm("cvt.rna.tf32.f32 %0, %1;" : "=r"(hb) : "f"(a));
    float hi = __uint_as_float(hb);
    float lo = a - hi;
    uint32_t lb;
    asm("cvt.rna.tf32.f32 %0, %1;" : "=r"(lb) : "f"(lo));
    return make_float2(hi, __uint_as_float(lb));
}
__device__ __forceinline__ float tf32rna(float a) {
    uint32_t b;
    asm("cvt.rna.tf32.f32 %0, %1;" : "=r"(b) : "f"(a));
    return __uint_as_float(b);
}
// m16n8k8 tf32 MMA (baseline PTX, works on compute_103)
__device__ __forceinline__ void mma8(float c[4], const float a[4], const float b[2]) {
    asm volatile(
        "mma.sync.aligned.m16n8k8.row.col.f32.tf32.tf32.f32 "
        "{%0,%1,%2,%3}, {%4,%5,%6,%7}, {%8,%9}, {%0,%1,%2,%3};"
        : "+f"(c[0]), "+f"(c[1]), "+f"(c[2]), "+f"(c[3])
        : "r"(__float_as_uint(a[0])), "r"(__float_as_uint(a[1])),
          "r"(__float_as_uint(a[2])), "r"(__float_as_uint(a[3])),
          "r"(__float_as_uint(b[0])), "r"(__float_as_uint(b[1])));
}

// ---------------------------------------------------------------------------
// Decomposition kernels
// ---------------------------------------------------------------------------
__global__ __launch_bounds__(256) void decomp_kernel(
    const float* __restrict__ src, float* __restrict__ hi, float* __restrict__ lo)
{
    int i = blockIdx.x * 256 + threadIdx.x;
    float4 v = ((const float4*)src)[i];
    float2 sx = tf32split(v.x), sy = tf32split(v.y);
    float2 sz = tf32split(v.z), sw = tf32split(v.w);
    ((float4*)hi)[i] = make_float4(sx.x, sy.x, sz.x, sw.x);
    ((float4*)lo)[i] = make_float4(sx.y, sy.y, sz.y, sw.y);
}

// W[k][n] -> hi/lo [n][k]
__global__ __launch_bounds__(256) void decomp_t_kernel(
    const float* __restrict__ src, float* __restrict__ dhi, float* __restrict__ dlo,
    int K, int N)
{
    __shared__ float t[32][33];
    int k0 = blockIdx.y * 32, n0 = blockIdx.x * 32;
    int r = threadIdx.x >> 3;
    int c4 = (threadIdx.x & 7) * 4;
    float4 v = *(const float4*)(src + (size_t)(k0 + r) * N + n0 + c4);
    t[r][c4 + 0] = v.x; t[r][c4 + 1] = v.y; t[r][c4 + 2] = v.z; t[r][c4 + 3] = v.w;
    __syncthreads();
    float2 s0 = tf32split(t[c4 + 0][r]);
    float2 s1 = tf32split(t[c4 + 1][r]);
    float2 s2 = tf32split(t[c4 + 2][r]);
    float2 s3 = tf32split(t[c4 + 3][r]);
    *(float4*)(dhi + (size_t)(n0 + r) * K + k0 + c4) =
        make_float4(s0.x, s1.x, s2.x, s3.x);
    *(float4*)(dlo + (size_t)(n0 + r) * K + k0 + c4) =
        make_float4(s0.y, s1.y, s2.y, s3.y);
}

// ---------------------------------------------------------------------------
// mma.sync tf32 3x GEMM (R12-proven: k16 chunks, CH_F=20, 2 stages, occ 2).
// MODE 0: out projection  (C -> Cout[m][n] + bias)
// MODE 1: qkv projection  (q,k fp32; v tf32-rounded)
// ---------------------------------------------------------------------------
#define CH_F 20
#define ARR_F (128 * CH_F)
#define STAGE_F (4 * ARR_F)
#define GEMM_SMEM_BYTES (2 * STAGE_F * 4)   // 81920
#define NCHUNK 64

template <int MODE>
__global__ __launch_bounds__(256, 2) void gemm_mma_kernel(
    const float* __restrict__ Ahi, const float* __restrict__ Alo,
    const float* __restrict__ Bhi, const float* __restrict__ Blo,
    const float* __restrict__ bias, float* __restrict__ Cout)
{
    extern __shared__ float gsm[];
    const uint32_t sbase = smem_u32(gsm);
    const int tid = threadIdx.x;
    const int wid = tid >> 5;
    const int lane = tid & 31;
    const int grp = lane >> 2;
    const int tg = lane & 3;
    const int n0 = blockIdx.x * 128;
    const int m0 = blockIdx.y * 128;

    const int lrow = tid >> 1;
    const int lg = (tid & 1) * 8;

    const float* srcA_hi = Ahi + (size_t)(m0 + lrow) * DM_ + lg;
    const float* srcA_lo = Alo + (size_t)(m0 + lrow) * DM_ + lg;
    const float* srcB_hi = Bhi + (size_t)(n0 + lrow) * DM_ + lg;
    const float* srcB_lo = Blo + (size_t)(n0 + lrow) * DM_ + lg;

    auto load_chunk = [&](int c) {
        if (c < NCHUNK) {
            const uint32_t sb = sbase + ((c & 1) * STAGE_F) * 4;
            const uint32_t dbase = sb + (lrow * CH_F + lg) * 4;
            const int k0 = c * 16;
            cpa16(dbase + 0 * ARR_F * 4,      srcA_hi + k0);
            cpa16(dbase + 0 * ARR_F * 4 + 16, srcA_hi + k0 + 4);
            cpa16(dbase + 1 * ARR_F * 4,      srcA_lo + k0);
            cpa16(dbase + 1 * ARR_F * 4 + 16, srcA_lo + k0 + 4);
            cpa16(dbase + 2 * ARR_F * 4,      srcB_hi + k0);
            cpa16(dbase + 2 * ARR_F * 4 + 16, srcB_hi + k0 + 4);
            cpa16(dbase + 3 * ARR_F * 4,      srcB_lo + k0);
            cpa16(dbase + 3 * ARR_F * 4 + 16, srcB_lo + k0 + 4);
        }
        asm volatile("cp.async.commit_group;" ::: "memory");
    };

    const int wm = wid & 1;
    const int wn = wid >> 1;

    float acc[4][4][4];
#pragma unroll
    for (int mf = 0; mf < 4; mf++)
#pragma unroll
        for (int nf = 0; nf < 4; nf++)
#pragma unroll
            for (int e = 0; e < 4; e++) acc[mf][nf][e] = 0.f;

    load_chunk(0);
    load_chunk(1);

    for (int c = 0; c < NCHUNK; c++) {
        asm volatile("cp.async.wait_group 1;" ::: "memory");
        __syncthreads();

        const float* sb = gsm + (c & 1) * STAGE_F;
        const float* sAhi = sb;
        const float* sAlo = sb + ARR_F;
        const float* sBhi = sb + 2 * ARR_F;
        const float* sBlo = sb + 3 * ARR_F;

#pragma unroll
        for (int k8 = 0; k8 < 2; k8++) {
            const int kk = k8 * 8;
            float aH[4][4], aL[4][4];
#pragma unroll
            for (int mf = 0; mf < 4; mf++) {
                int mr = wm * 64 + mf * 16 + grp;
                aH[mf][0] = sAhi[(mr) * CH_F + kk + tg];
                aH[mf][1] = sAhi[(mr + 8) * CH_F + kk + tg];
                aH[mf][2] = sAhi[(mr) * CH_F + kk + tg + 4];
                aH[mf][3] = sAhi[(mr + 8) * CH_F + kk + tg + 4];
                aL[mf][0] = sAlo[(mr) * CH_F + kk + tg];
                aL[mf][1] = sAlo[(mr + 8) * CH_F + kk + tg];
                aL[mf][2] = sAlo[(mr) * CH_F + kk + tg + 4];
                aL[mf][3] = sAlo[(mr + 8) * CH_F + kk + tg + 4];
            }
            float bH[4][2], bL[4][2];
#pragma unroll
            for (int nf = 0; nf < 4; nf++) {
                int nr = wn * 32 + nf * 8 + grp;
                bH[nf][0] = sBhi[nr * CH_F + kk + tg];
                bH[nf][1] = sBhi[nr * CH_F + kk + tg + 4];
                bL[nf][0] = sBlo[nr * CH_F + kk + tg];
                bL[nf][1] = sBlo[nr * CH_F + kk + tg + 4];
            }
#pragma unroll
            for (int mf = 0; mf < 4; mf++)
#pragma unroll
                for (int nf = 0; nf < 4; nf++) {
                    mma8(acc[mf][nf], aH[mf], bH[nf]);
                    mma8(acc[mf][nf], aH[mf], bL[nf]);
                    mma8(acc[mf][nf], aL[mf], bH[nf]);
                }
        }
        __syncthreads();
        load_chunk(c + 2);
    }

#pragma unroll
    for (int mf = 0; mf < 4; mf++) {
#pragma unroll
        for (int nf = 0; nf < 4; nf++) {
            int m = m0 + wm * 64 + mf * 16 + grp;
            int n = n0 + wn * 32 + nf * 8 + tg * 2;
            float b0 = __ldg(bias + n), b1 = __ldg(bias + n + 1);
            float2 v0 = make_float2(acc[mf][nf][0] + b0, acc[mf][nf][1] + b1);
            float2 v1 = make_float2(acc[mf][nf][2] + b0, acc[mf][nf][3] + b1);
            if (MODE == 0) {
                *(float2*)(Cout + (size_t)m * DM_ + n) = v0;
                *(float2*)(Cout + (size_t)(m + 8) * DM_ + n) = v1;
            } else {
                int mat = n >> 10;
                int cc = n & 1023;
                int h = cc >> 6, dd = cc & 63;
                int bidx = m >> 11;
                int l = m & 2047;
                size_t i0 = (((size_t)(bidx * H_ + h)) * L_ + l) * DH_ + dd;
                size_t i1 = (((size_t)(bidx * H_ + h)) * L_ + l + 8) * DH_ + dd;
                if (mat == 0) {
                    *(float2*)(g_q + i0) = v0;
                    *(float2*)(g_q + i1) = v1;
                } else if (mat == 1) {
                    *(float2*)(g_k + i0) = v0;
                    *(float2*)(g_k + i1) = v1;
                } else {
                    *(float2*)(g_v + i0) = make_float2(tf32rna(v0.x), tf32rna(v0.y));
                    *(float2*)(g_v + i1) = make_float2(tf32rna(v1.x), tf32rna(v1.y));
                }
            }
        }
    }
}

// ---------------------------------------------------------------------------
// Attention, two-pass, tensor-pipe, double-buffered tiles.
// 128 q-rows/CTA, 64-key tiles, 8 warps; warp tile 16 rows x 64 keys
// (each warp owns its rows across ALL keys -> rowsums are warp-local).
// Pass A: K only; scores+exp -> rowsums in regs (no stores).
// Pass B: K+V; recompute scores+exp (deterministic), scale by inv at store
//         -> attn written ONCE (final); AV on normalized fragments.
// Eliminates the 2.15 GB rescale read+write traffic.
// smem: sq[128][68] + 2 x (K[64][68] + V[64][68]) = 104448 B -> occ 2
// ---------------------------------------------------------------------------
#define SQ_F (128 * 68)
#define TK_F (64 * 68)
#define ATTN_SMEM_FLOATS (SQ_F + 4 * TK_F)
#define ATTN_SMEM_BYTES  (ATTN_SMEM_FLOATS * 4)   // 104448

__global__ __launch_bounds__(256, 2) void attn_kernel(float* __restrict__ attn_out)
{
    extern __shared__ float sm[];
    float* sq = sm;                         // [row][d] stride 68 fp32
    const uint32_t sb = smem_u32(sm);

    const int tid = threadIdx.x;
    const int wid = tid >> 5;
    const int lane = tid & 31;
    const int grp = lane >> 2;
    const int tg = lane & 3;
    const int mr = wid * 16 + grp;

    const int bh = blockIdx.y;
    const int q0 = blockIdx.x * 128;
    const size_t base = (size_t)bh * L_ * DH_;
    float* attn = attn_out + (size_t)bh * L_ * L_;

    const int klr = tid >> 2;          // 0..63 key row
    const int kc = (tid & 3) * 16;     // col group (64 B aligned)

    // K-only tile load (pass A)
    auto load_k = [&](int kt) {
        if (kt < L_ / 64) {
            int s = kt & 1;
            const float* pk = g_k + base + (size_t)(kt * 64 + klr) * DH_ + kc;
            uint32_t dk = sb + (SQ_F + s * 2 * TK_F + klr * 68 + kc) * 4;
#pragma unroll
            for (int j = 0; j < 4; j++) cpa16(dk + j * 16, pk + j * 4);
        }
        asm volatile("cp.async.commit_group;" ::: "memory");
    };
    // K+V tile load (pass B)
    auto load_kv = [&](int kt) {
        if (kt < L_ / 64) {
            int s = kt & 1;
            const float* pk = g_k + base + (size_t)(kt * 64 + klr) * DH_ + kc;
            const float* pv = g_v + base + (size_t)(kt * 64 + klr) * DH_ + kc;
            uint32_t dk = sb + (SQ_F + s * 2 * TK_F + klr * 68 + kc) * 4;
            uint32_t dv = dk + TK_F * 4;
#pragma unroll
            for (int j = 0; j < 4; j++) {
                cpa16(dk + j * 16, pk + j * 4);
                cpa16(dv + j * 16, pv + j * 4);
            }
        }
        asm volatile("cp.async.commit_group;" ::: "memory");
    };

    // scores for one tile (stage s): 3xTF32, returns exp'ed C-frags
    auto score_tile = [&](int s, float c[8][4]) {
        const float* sK = sm + SQ_F + s * 2 * TK_F;
#pragma unroll
        for (int nf = 0; nf < 8; nf++)
#pragma unroll
            for (int e = 0; e < 4; e++) c[nf][e] = 0.f;
#pragma unroll
        for (int k8 = 0; k8 < 8; k8++) {
            const int kk = k8 * 8;
            float af[4], aH[4], aL[4];
            af[0] = sq[(mr) * 68 + kk + tg];
            af[1] = sq[(mr + 8) * 68 + kk + tg];
            af[2] = sq[(mr) * 68 + kk + tg + 4];
            af[3] = sq[(mr + 8) * 68 + kk + tg + 4];
#pragma unroll
            for (int e = 0; e < 4; e++) {
                aH[e] = tf32rna(af[e]);
                aL[e] = tf32rna(af[e] - aH[e]);
            }
#pragma unroll
            for (int nf = 0; nf < 8; nf++) {
                int nr = nf * 8 + grp;
                float bf0 = sK[nr * 68 + kk + tg];
                float bf1 = sK[nr * 68 + kk + tg + 4];
                float bH[2], bL[2];
                bH[0] = tf32rna(bf0); bL[0] = tf32rna(bf0 - bH[0]);
                bH[1] = tf32rna(bf1); bL[1] = tf32rna(bf1 - bH[1]);
                mma8(c[nf], aH, bH);
                mma8(c[nf], aL, bH);
                mma8(c[nf], aH, bL);
            }
        }
#pragma unroll
        for (int nf = 0; nf < 8; nf++) {
            c[nf][0] = __expf(c[nf][0] * 0.125f);
            c[nf][1] = __expf(c[nf][1] * 0.125f);
            c[nf][2] = __expf(c[nf][2] * 0.125f);
            c[nf][3] = __expf(c[nf][3] * 0.125f);
        }
    };

    // Q tile load (one-time) + tile 0 prefetch
    {
        int lr = tid >> 1;
        int lc = (tid & 1) * 32;
        const float* src = g_q + base + (size_t)(q0 + lr) * DH_ + lc;
        uint32_t dst = sb + (lr * 68 + lc) * 4;
#pragma unroll
        for (int j = 0; j < 8; j++) cpa16(dst + j * 16, src + j * 4);
        asm volatile("cp.async.commit_group;" ::: "memory");
    }
    load_k(0);

    // ---- Pass A: rowsums only ----
    float rsum0 = 0.f, rsum1 = 0.f;
    for (int kt = 0; kt < L_ / 64; kt++) {
        load_k(kt + 1);
        asm volatile("cp.async.wait_group 1;" ::: "memory");
        __syncthreads();
        float c[8][4];
        score_tile(kt & 1, c);
        float rs0 = 0.f, rs1 = 0.f;
#pragma unroll
        for (int nf = 0; nf < 8; nf++) {
            rs0 += c[nf][0] + c[nf][1];
            rs1 += c[nf][2] + c[nf][3];
        }
        rsum0 += rs0;
        rsum1 += rs1;
        __syncthreads();
    }
    rsum0 += __shfl_xor_sync(0xffffffffu, rsum0, 1);
    rsum0 += __shfl_xor_sync(0xffffffffu, rsum0, 2);
    rsum1 += __shfl_xor_sync(0xffffffffu, rsum1, 1);
    rsum1 += __shfl_xor_sync(0xffffffffu, rsum1, 2);
    const float inv0 = 1.f / rsum0;
    const float inv1 = 1.f / rsum1;

    asm volatile("cp.async.wait_group 0;" ::: "memory");
    __syncthreads();

    // ---- Pass B: normalized store + AV ----
    float o[8][4];
#pragma unroll
    for (int j = 0; j < 8; j++)
#pragma unroll
        for (int e = 0; e < 4; e++) o[j][e] = 0.f;

    load_kv(0);
    for (int kt = 0; kt < L_ / 64; kt++) {
        const int k0g = kt * 64;
        load_kv(kt + 1);
        asm volatile("cp.async.wait_group 1;" ::: "memory");
        __syncthreads();

        const int s = kt & 1;
        const float* sV = sm + SQ_F + s * 2 * TK_F + TK_F;

        float c[8][4];
        score_tile(s, c);

        // normalized store (single, final)
#pragma unroll
        for (int nf = 0; nf < 8; nf++) {
            int n = k0g + nf * 8 + tg * 2;
            *(float2*)(attn + (size_t)(q0 + mr) * L_ + n) =
                make_float2(c[nf][0] * inv0, c[nf][1] * inv0);
            *(float2*)(attn + (size_t)(q0 + mr + 8) * L_ + n) =
                make_float2(c[nf][2] * inv1, c[nf][3] * inv1);
        }

        // AV on normalized fragments: C-frag -> A-frag via quad shuffles
        const int s1 = (lane & ~3) | (tg >> 1);
        const int s2 = s1 + 2;
        const bool odd = tg & 1;
#pragma unroll
        for (int nf = 0; nf < 8; nf++) {
            float v0 = __shfl_sync(0xffffffffu, c[nf][0], s1);
            float v1 = __shfl_sync(0xffffffffu, c[nf][1], s1);
            float v2 = __shfl_sync(0xffffffffu, c[nf][2], s1);
            float v3 = __shfl_sync(0xffffffffu, c[nf][3], s1);
            float w0 = __shfl_sync(0xffffffffu, c[nf][0], s2);
            float w1 = __shfl_sync(0xffffffffu, c[nf][1], s2);
            float w2 = __shfl_sync(0xffffffffu, c[nf][2], s2);
            float w3 = __shfl_sync(0xffffffffu, c[nf][3], s2);
            float a[4];
            a[0] = tf32rna((odd ? v1 : v0) * inv0);
            a[1] = tf32rna((odd ? v3 : v2) * inv1);
            a[2] = tf32rna((odd ? w1 : w0) * inv0);
            a[3] = tf32rna((odd ? w3 : w2) * inv1);
            const int kk = nf * 8;
#pragma unroll
            for (int j = 0; j < 8; j++) {
                float b[2];
                b[0] = sV[(kk + tg) * 68 + j * 8 + grp];
                b[1] = sV[(kk + tg + 4) * 68 + j * 8 + grp];
                mma8(o[j], a, b);
            }
        }
        __syncthreads();
    }

    const int bidx = bh >> 4;
    const int h = bh & 15;

    // O epilogue (already normalized): tf32split -> g_hhi/g_hlo
    {
        size_t r0 = ((size_t)(bidx * L_) + q0 + mr) * DM_ + h * DH_;
        size_t r1 = r0 + (size_t)8 * DM_;
#pragma unroll
        for (int j = 0; j < 8; j++) {
            int nd = j * 8 + tg * 2;
            float2 sx = tf32split(o[j][0]);
            float2 sy = tf32split(o[j][1]);
            *(float2*)(g_hhi + r0 + nd) = make_float2(sx.x, sy.x);
            *(float2*)(g_hlo + r0 + nd) = make_float2(sx.y, sy.y);
            sx = tf32split(o[j][2]);
            sy = tf32split(o[j][3]);
            *(float2*)(g_hhi + r1 + nd) = make_float2(sx.x, sy.x);
            *(float2*)(g_hlo + r1 + nd) = make_float2(sx.y, sy.y);
        }
    }
}

// ---------------------------------------------------------------------------
extern "C" void kernel_launch(void* const* d_in, const int* in_sizes, int n_in,
                              void* d_out, int out_size)
{
    (void)in_sizes; (void)n_in; (void)out_size;
    const float* x    = (const float*)d_in[0];
    const float* Wqkv = (const float*)d_in[1];
    const float* bqkv = (const float*)d_in[2];
    const float* Wout = (const float*)d_in[3];
    const float* bout = (const float*)d_in[4];
    float* out  = (float*)d_out;
    float* attn = out + OUT_ELEMS_;

    static int attr_done = 0;
    if (!attr_done) {
        cudaFuncSetAttribute(attn_kernel,
            cudaFuncAttributeMaxDynamicSharedMemorySize, ATTN_SMEM_BYTES);
        cudaFuncSetAttribute(gemm_mma_kernel<0>,
            cudaFuncAttributeMaxDynamicSharedMemorySize, GEMM_SMEM_BYTES);
        cudaFuncSetAttribute(gemm_mma_kernel<1>,
            cudaFuncAttributeMaxDynamicSharedMemorySize, GEMM_SMEM_BYTES);
        attr_done = 1;
    }

    float *xhi, *xlo, *wqhi, *wqlo, *wohi, *wolo, *hhi, *hlo;
    cudaGetSymbolAddress((void**)&xhi,  g_xhi);
    cudaGetSymbolAddress((void**)&xlo,  g_xlo);
    cudaGetSymbolAddress((void**)&wqhi, g_wqhi);
    cudaGetSymbolAddress((void**)&wqlo, g_wqlo);
    cudaGetSymbolAddress((void**)&wohi, g_wohi);
    cudaGetSymbolAddress((void**)&wolo, g_wolo);
    cudaGetSymbolAddress((void**)&hhi,  g_hhi);
    cudaGetSymbolAddress((void**)&hlo,  g_hlo);

    // operand decompositions
    decomp_kernel<<<OUT_ELEMS_ / 4 / 256, 256>>>(x, xhi, xlo);
    decomp_t_kernel<<<dim3(N3_ / 32, DM_ / 32), 256>>>(Wqkv, wqhi, wqlo, DM_, N3_);
    decomp_t_kernel<<<dim3(DM_ / 32, DM_ / 32), 256>>>(Wout, wohi, wolo, DM_, DM_);

    // QKV projection (q,k fp32; v tf32-rounded)
    gemm_mma_kernel<1><<<dim3(N3_ / 128, (B_ * L_) / 128), 256, GEMM_SMEM_BYTES>>>(
        xhi, xlo, wqhi, wqlo, bqkv, nullptr);

    // attention: two-pass, single normalized attn store
    attn_kernel<<<dim3(L_ / 128, BH_), 256, ATTN_SMEM_BYTES>>>(attn);

    // out projection (reads pre-split hhi/hlo straight from attn)
    gemm_mma_kernel<0><<<dim3(DM_ / 128, (B_ * L_) / 128), 256, GEMM_SMEM_BYTES>>>(
        hhi, hlo, wohi, wolo, bout, out);
}

// round 16
// speedup vs baseline: 1.3135x; 1.3135x over previous
#include <cuda_runtime.h>
#include <cstdint>

#define B_ 4
#define L_ 2048
#define H_ 16
#define DH_ 64
#define DM_ 1024
#define N3_ 3072
#define BH_ (B_*H_)
#define OUT_ELEMS_ (B_*L_*DM_)   // 8388608

// Scratch (device globals: allocation-free per harness rules)
__device__ float g_q[BH_*L_*DH_];     // fp32
__device__ float g_k[BH_*L_*DH_];     // fp32 (split to tf32 hi/lo in regs)
__device__ float g_v[BH_*L_*DH_];     // pre-rounded tf32 (rna)
__device__ float g_hout[B_*L_*DM_];   // attn output head-merged, fp32
__device__ float g_wqT[N3_*DM_];      // W_qkv transposed [n][k] fp32
__device__ float g_woT[DM_*DM_];      // W_out transposed [n][k] fp32

// ---------------------------------------------------------------------------
// Helpers
// ---------------------------------------------------------------------------
__device__ __forceinline__ uint32_t smem_u32(const void* p) {
    uint32_t a;
    asm("{ .reg .u64 t; cvta.to.shared.u64 t, %1; cvt.u32.u64 %0, t; }"
        : "=r"(a) : "l"(p));
    return a;
}
__device__ __forceinline__ void cpa16(uint32_t dst, const float* src) {
    asm volatile("cp.async.cg.shared.global [%0], [%1], 16;" :: "r"(dst), "l"(src));
}
__device__ __forceinline__ float tf32rna(float a) {
    uint32_t b;
    asm("cvt.rna.tf32.f32 %0, %1;" : "=r"(b) : "f"(a));
    return __uint_as_float(b);
}
// m16n8k8 tf32 MMA (baseline PTX, works on compute_103)
__device__ __forceinline__ void mma8(float c[4], const float a[4], const float b[2]) {
    asm volatile(
        "mma.sync.aligned.m16n8k8.row.col.f32.tf32.tf32.f32 "
        "{%0,%1,%2,%3}, {%4,%5,%6,%7}, {%8,%9}, {%0,%1,%2,%3};"
        : "+f"(c[0]), "+f"(c[1]), "+f"(c[2]), "+f"(c[3])
        : "r"(__float_as_uint(a[0])), "r"(__float_as_uint(a[1])),
          "r"(__float_as_uint(a[2])), "r"(__float_as_uint(a[3])),
          "r"(__float_as_uint(b[0])), "r"(__float_as_uint(b[1])));
}

// ---------------------------------------------------------------------------
// Transpose kernel: W[k][n] -> [n][k] fp32 (no split; split happens in regs)
// ---------------------------------------------------------------------------
__global__ __launch_bounds__(256) void transpose_kernel(
    const float* __restrict__ src, float* __restrict__ dst, int K, int N)
{
    __shared__ float t[32][33];
    int k0 = blockIdx.y * 32, n0 = blockIdx.x * 32;
    int r = threadIdx.x >> 3;
    int c4 = (threadIdx.x & 7) * 4;
    float4 v = *(const float4*)(src + (size_t)(k0 + r) * N + n0 + c4);
    t[r][c4 + 0] = v.x; t[r][c4 + 1] = v.y; t[r][c4 + 2] = v.z; t[r][c4 + 3] = v.w;
    __syncthreads();
    *(float4*)(dst + (size_t)(n0 + r) * K + k0 + c4) =
        make_float4(t[c4 + 0][r], t[c4 + 1][r], t[c4 + 2][r], t[c4 + 3][r]);
}

// ---------------------------------------------------------------------------
// mma.sync tf32 3x GEMM, fp32 operands in smem, hi/lo split in registers.
// k16 chunks, 4-stage cp.async pipeline, 80 KB smem -> 2 CTA/SM.
// MODE 0: out projection  (C -> Cout[m][n] + bias)
// MODE 1: qkv projection  (q,k fp32; v tf32-rounded)
// ---------------------------------------------------------------------------
#define CH_F 20                         // row stride (16 + 4 pad); 80 B (16B-mult!)
#define ARR_F (128 * CH_F)              // 2560 floats per operand array
#define STAGE_F (2 * ARR_F)             // 5120 floats (A + B)
#define NSTAGE 4
#define GEMM_SMEM_BYTES (NSTAGE * STAGE_F * 4)   // 81920
#define NCHUNK 64

template <int MODE>
__global__ __launch_bounds__(256, 2) void gemm_mma_kernel(
    const float* __restrict__ A, const float* __restrict__ Bm,
    const float* __restrict__ bias, float* __restrict__ Cout)
{
    extern __shared__ float gsm[];
    const uint32_t sbase = smem_u32(gsm);
    const int tid = threadIdx.x;
    const int wid = tid >> 5;
    const int lane = tid & 31;
    const int grp = lane >> 2;
    const int tg = lane & 3;
    const int n0 = blockIdx.x * 128;
    const int m0 = blockIdx.y * 128;

    const int lrow = tid >> 1;
    const int lg = (tid & 1) * 8;

    const float* srcA = A  + (size_t)(m0 + lrow) * DM_ + lg;
    const float* srcB = Bm + (size_t)(n0 + lrow) * DM_ + lg;

    auto load_chunk = [&](int c) {
        if (c < NCHUNK) {
            const uint32_t sb = sbase + ((c % NSTAGE) * STAGE_F) * 4;
            const uint32_t dbase = sb + (lrow * CH_F + lg) * 4;
            const int k0 = c * 16;
            cpa16(dbase,                      srcA + k0);
            cpa16(dbase + 16,                 srcA + k0 + 4);
            cpa16(dbase + ARR_F * 4,          srcB + k0);
            cpa16(dbase + ARR_F * 4 + 16,     srcB + k0 + 4);
        }
        asm volatile("cp.async.commit_group;" ::: "memory");
    };

    const int wm = wid & 1;
    const int wn = wid >> 1;

    float acc[4][4][4];
#pragma unroll
    for (int mf = 0; mf < 4; mf++)
#pragma unroll
        for (int nf = 0; nf < 4; nf++)
#pragma unroll
            for (int e = 0; e < 4; e++) acc[mf][nf][e] = 0.f;

    load_chunk(0);
    load_chunk(1);
    load_chunk(2);

    for (int c = 0; c < NCHUNK; c++) {
        asm volatile("cp.async.wait_group 2;" ::: "memory");
        __syncthreads();

        const float* sb = gsm + (c % NSTAGE) * STAGE_F;
        const float* sA = sb;
        const float* sB = sb + ARR_F;

#pragma unroll
        for (int k8 = 0; k8 < 2; k8++) {
            const int kk = k8 * 8;
            float aH[4][4], aL[4][4];
#pragma unroll
            for (int mf = 0; mf < 4; mf++) {
                int mr = wm * 64 + mf * 16 + grp;
                float a0 = sA[(mr) * CH_F + kk + tg];
                float a1 = sA[(mr + 8) * CH_F + kk + tg];
                float a2 = sA[(mr) * CH_F + kk + tg + 4];
                float a3 = sA[(mr + 8) * CH_F + kk + tg + 4];
                aH[mf][0] = tf32rna(a0); aL[mf][0] = tf32rna(a0 - aH[mf][0]);
                aH[mf][1] = tf32rna(a1); aL[mf][1] = tf32rna(a1 - aH[mf][1]);
                aH[mf][2] = tf32rna(a2); aL[mf][2] = tf32rna(a2 - aH[mf][2]);
                aH[mf][3] = tf32rna(a3); aL[mf][3] = tf32rna(a3 - aH[mf][3]);
            }
            float bH[4][2], bL[4][2];
#pragma unroll
            for (int nf = 0; nf < 4; nf++) {
                int nr = wn * 32 + nf * 8 + grp;
                float b0 = sB[nr * CH_F + kk + tg];
                float b1 = sB[nr * CH_F + kk + tg + 4];
                bH[nf][0] = tf32rna(b0); bL[nf][0] = tf32rna(b0 - bH[nf][0]);
                bH[nf][1] = tf32rna(b1); bL[nf][1] = tf32rna(b1 - bH[nf][1]);
            }
#pragma unroll
            for (int mf = 0; mf < 4; mf++)
#pragma unroll
                for (int nf = 0; nf < 4; nf++) {
                    mma8(acc[mf][nf], aH[mf], bH[nf]);
                    mma8(acc[mf][nf], aH[mf], bL[nf]);
                    mma8(acc[mf][nf], aL[mf], bH[nf]);
                }
        }
        __syncthreads();
        load_chunk(c + 3);
    }

#pragma unroll
    for (int mf = 0; mf < 4; mf++) {
#pragma unroll
        for (int nf = 0; nf < 4; nf++) {
            int m = m0 + wm * 64 + mf * 16 + grp;
            int n = n0 + wn * 32 + nf * 8 + tg * 2;
            float b0 = __ldg(bias + n), b1 = __ldg(bias + n + 1);
            float2 v0 = make_float2(acc[mf][nf][0] + b0, acc[mf][nf][1] + b1);
            float2 v1 = make_float2(acc[mf][nf][2] + b0, acc[mf][nf][3] + b1);
            if (MODE == 0) {
                *(float2*)(Cout + (size_t)m * DM_ + n) = v0;
                *(float2*)(Cout + (size_t)(m + 8) * DM_ + n) = v1;
            } else {
                int mat = n >> 10;
                int cc = n & 1023;
                int h = cc >> 6, dd = cc & 63;
                int bidx = m >> 11;
                int l = m & 2047;
                size_t i0 = (((size_t)(bidx * H_ + h)) * L_ + l) * DH_ + dd;
                size_t i1 = (((size_t)(bidx * H_ + h)) * L_ + l + 8) * DH_ + dd;
                if (mat == 0) {
                    *(float2*)(g_q + i0) = v0;
                    *(float2*)(g_q + i1) = v1;
                } else if (mat == 1) {
                    *(float2*)(g_k + i0) = v0;
                    *(float2*)(g_k + i1) = v1;
                } else {
                    *(float2*)(g_v + i0) = make_float2(tf32rna(v0.x), tf32rna(v0.y));
                    *(float2*)(g_v + i1) = make_float2(tf32rna(v1.x), tf32rna(v1.y));
                }
            }
        }
    }
}

// ---------------------------------------------------------------------------
// Attention (R14-proven best): tensor-pipe, double-buffered K/V, single pass,
// fused rescale. Epilogue now writes plain fp32 g_hout (out-GEMM splits in
// regs), halving hout store traffic.
// smem: sq[128][68] + 2 x (K[64][68] + V[64][68]) + srow[128] = 104960 B
// ---------------------------------------------------------------------------
#define SQ_F (128 * 68)
#define TK_F (64 * 68)
#define ATTN_SMEM_FLOATS (SQ_F + 4 * TK_F + 128)
#define ATTN_SMEM_BYTES  (ATTN_SMEM_FLOATS * 4)   // 104960

__global__ __launch_bounds__(256, 2) void attn_kernel(float* __restrict__ attn_out)
{
    extern __shared__ float sm[];
    float* sq   = sm;                       // [row][d] stride 68 fp32
    float* srow = sm + SQ_F + 4 * TK_F;     // [128]
    const uint32_t sb = smem_u32(sm);

    const int tid = threadIdx.x;
    const int wid = tid >> 5;
    const int lane = tid & 31;
    const int grp = lane >> 2;
    const int tg = lane & 3;
    const int mr = wid * 16 + grp;

    const int bh = blockIdx.y;
    const int q0 = blockIdx.x * 128;
    const size_t base = (size_t)bh * L_ * DH_;
    float* attn = attn_out + (size_t)bh * L_ * L_;

    const int klr = tid >> 2;
    const int kc = (tid & 3) * 16;

    auto load_tile = [&](int kt) {
        if (kt < L_ / 64) {
            int s = kt & 1;
            const float* pk = g_k + base + (size_t)(kt * 64 + klr) * DH_ + kc;
            const float* pv = g_v + base + (size_t)(kt * 64 + klr) * DH_ + kc;
            uint32_t dk = sb + (SQ_F + s * 2 * TK_F + klr * 68 + kc) * 4;
            uint32_t dv = dk + TK_F * 4;
#pragma unroll
            for (int j = 0; j < 4; j++) {
                cpa16(dk + j * 16, pk + j * 4);
                cpa16(dv + j * 16, pv + j * 4);
            }
        }
        asm volatile("cp.async.commit_group;" ::: "memory");
    };

    {
        int lr = tid >> 1;
        int lc = (tid & 1) * 32;
        const float* src = g_q + base + (size_t)(q0 + lr) * DH_ + lc;
        uint32_t dst = sb + (lr * 68 + lc) * 4;
#pragma unroll
        for (int j = 0; j < 8; j++) cpa16(dst + j * 16, src + j * 4);
        asm volatile("cp.async.commit_group;" ::: "memory");
    }
    load_tile(0);

    float o[8][4];
#pragma unroll
    for (int j = 0; j < 8; j++)
#pragma unroll
        for (int e = 0; e < 4; e++) o[j][e] = 0.f;
    float rsum0 = 0.f, rsum1 = 0.f;

    for (int kt = 0; kt < L_ / 64; kt++) {
        const int k0g = kt * 64;
        load_tile(kt + 1);
        asm volatile("cp.async.wait_group 1;" ::: "memory");
        __syncthreads();

        const int s = kt & 1;
        const float* sK = sm + SQ_F + s * 2 * TK_F;
        const float* sV = sK + TK_F;

        float c[8][4];
#pragma unroll
        for (int nf = 0; nf < 8; nf++)
#pragma unroll
            for (int e = 0; e < 4; e++) c[nf][e] = 0.f;

#pragma unroll
        for (int k8 = 0; k8 < 8; k8++) {
            const int kk = k8 * 8;
            float af[4], aH[4], aL[4];
            af[0] = sq[(mr) * 68 + kk + tg];
            af[1] = sq[(mr + 8) * 68 + kk + tg];
            af[2] = sq[(mr) * 68 + kk + tg + 4];
            af[3] = sq[(mr + 8) * 68 + kk + tg + 4];
#pragma unroll
            for (int e = 0; e < 4; e++) {
                aH[e] = tf32rna(af[e]);
                aL[e] = tf32rna(af[e] - aH[e]);
            }
#pragma unroll
            for (int nf = 0; nf < 8; nf++) {
                int nr = nf * 8 + grp;
                float bf0 = sK[nr * 68 + kk + tg];
                float bf1 = sK[nr * 68 + kk + tg + 4];
                float bH[2], bL[2];
                bH[0] = tf32rna(bf0); bL[0] = tf32rna(bf0 - bH[0]);
                bH[1] = tf32rna(bf1); bL[1] = tf32rna(bf1 - bH[1]);
                mma8(c[nf], aH, bH);
                mma8(c[nf], aL, bH);
                mma8(c[nf], aH, bL);
            }
        }

        {
            float rs0 = 0.f, rs1 = 0.f;
#pragma unroll
            for (int nf = 0; nf < 8; nf++) {
                float e0 = __expf(c[nf][0] * 0.125f);
                float e1 = __expf(c[nf][1] * 0.125f);
                float e2 = __expf(c[nf][2] * 0.125f);
                float e3 = __expf(c[nf][3] * 0.125f);
                c[nf][0] = e0; c[nf][1] = e1; c[nf][2] = e2; c[nf][3] = e3;
                rs0 += e0 + e1;
                rs1 += e2 + e3;
                int n = k0g + nf * 8 + tg * 2;
                *(float2*)(attn + (size_t)(q0 + mr) * L_ + n) = make_float2(e0, e1);
                *(float2*)(attn + (size_t)(q0 + mr + 8) * L_ + n) = make_float2(e2, e3);
            }
            rs0 += __shfl_xor_sync(0xffffffffu, rs0, 1);
            rs0 += __shfl_xor_sync(0xffffffffu, rs0, 2);
            rs1 += __shfl_xor_sync(0xffffffffu, rs1, 1);
            rs1 += __shfl_xor_sync(0xffffffffu, rs1, 2);
            rsum0 += rs0;
            rsum1 += rs1;
        }

        const int s1 = (lane & ~3) | (tg >> 1);
        const int s2 = s1 + 2;
        const bool odd = tg & 1;
#pragma unroll
        for (int nf = 0; nf < 8; nf++) {
            float v0 = __shfl_sync(0xffffffffu, c[nf][0], s1);
            float v1 = __shfl_sync(0xffffffffu, c[nf][1], s1);
            float v2 = __shfl_sync(0xffffffffu, c[nf][2], s1);
            float v3 = __shfl_sync(0xffffffffu, c[nf][3], s1);
            float w0 = __shfl_sync(0xffffffffu, c[nf][0], s2);
            float w1 = __shfl_sync(0xffffffffu, c[nf][1], s2);
            float w2 = __shfl_sync(0xffffffffu, c[nf][2], s2);
            float w3 = __shfl_sync(0xffffffffu, c[nf][3], s2);
            float a[4];
            a[0] = tf32rna(odd ? v1 : v0);
            a[1] = tf32rna(odd ? v3 : v2);
            a[2] = tf32rna(odd ? w1 : w0);
            a[3] = tf32rna(odd ? w3 : w2);
            const int kk = nf * 8;
#pragma unroll
            for (int j = 0; j < 8; j++) {
                float b[2];
                b[0] = sV[(kk + tg) * 68 + j * 8 + grp];
                b[1] = sV[(kk + tg + 4) * 68 + j * 8 + grp];
                mma8(o[j], a, b);
            }
        }
        __syncthreads();
    }

    if (tg == 0) {
        srow[wid * 16 + grp] = rsum0;
        srow[wid * 16 + grp + 8] = rsum1;
    }
    __syncthreads();

    const int bidx = bh >> 4;
    const int h = bh & 15;

    // O epilogue: normalize, write plain fp32 hout
    {
        float i0 = 1.f / srow[wid * 16 + grp];
        float i1 = 1.f / srow[wid * 16 + grp + 8];
        size_t r0 = ((size_t)(bidx * L_) + q0 + mr) * DM_ + h * DH_;
        size_t r1 = r0 + (size_t)8 * DM_;
#pragma unroll
        for (int j = 0; j < 8; j++) {
            int nd = j * 8 + tg * 2;
            *(float2*)(g_hout + r0 + nd) =
                make_float2(o[j][0] * i0, o[j][1] * i0);
            *(float2*)(g_hout + r1 + nd) =
                make_float2(o[j][2] * i1, o[j][3] * i1);
        }
    }

    // fused rescale of this CTA's 128 attn rows
    {
        const int ty = tid >> 4;
        const int tx = tid & 15;
#pragma unroll
        for (int i = 0; i < 8; i++) {
            float inv = 1.f / srow[ty * 8 + i];
            float* rowp = attn + (size_t)(q0 + ty * 8 + i) * L_;
#pragma unroll 4
            for (int j = 0; j < 32; j++) {
                float4* p = (float4*)(rowp + j * 64 + tx * 4);
                float4 v = *p;
                v.x *= inv; v.y *= inv; v.z *= inv; v.w *= inv;
                *p = v;
            }
        }
    }
}

// ---------------------------------------------------------------------------
extern "C" void kernel_launch(void* const* d_in, const int* in_sizes, int n_in,
                              void* d_out, int out_size)
{
    (void)in_sizes; (void)n_in; (void)out_size;
    const float* x    = (const float*)d_in[0];
    const float* Wqkv = (const float*)d_in[1];
    const float* bqkv = (const float*)d_in[2];
    const float* Wout = (const float*)d_in[3];
    const float* bout = (const float*)d_in[4];
    float* out  = (float*)d_out;
    float* attn = out + OUT_ELEMS_;

    static int attr_done = 0;
    if (!attr_done) {
        cudaFuncSetAttribute(attn_kernel,
            cudaFuncAttributeMaxDynamicSharedMemorySize, ATTN_SMEM_BYTES);
        cudaFuncSetAttribute(gemm_mma_kernel<0>,
            cudaFuncAttributeMaxDynamicSharedMemorySize, GEMM_SMEM_BYTES);
        cudaFuncSetAttribute(gemm_mma_kernel<1>,
            cudaFuncAttributeMaxDynamicSharedMemorySize, GEMM_SMEM_BYTES);
        attr_done = 1;
    }

    float *wqT, *woT, *hout;
    cudaGetSymbolAddress((void**)&wqT,  g_wqT);
    cudaGetSymbolAddress((void**)&woT,  g_woT);
    cudaGetSymbolAddress((void**)&hout, g_hout);

    // weight transposes (no decomposition needed; split happens in regs)
    transpose_kernel<<<dim3(N3_ / 32, DM_ / 32), 256>>>(Wqkv, wqT, DM_, N3_);
    transpose_kernel<<<dim3(DM_ / 32, DM_ / 32), 256>>>(Wout, woT, DM_, DM_);

    // QKV projection (A = x directly)
    gemm_mma_kernel<1><<<dim3(N3_ / 128, (B_ * L_) / 128), 256, GEMM_SMEM_BYTES>>>(
        x, wqT, bqkv, nullptr);

    // attention (R14-proven) + fused rescale
    attn_kernel<<<dim3(L_ / 128, BH_), 256, ATTN_SMEM_BYTES>>>(attn);

    // out projection (A = hout directly)
    gemm_mma_kernel<0><<<dim3(DM_ / 128, (B_ * L_) / 128), 256, GEMM_SMEM_BYTES>>>(
        hout, woT, bout, out);
}